// round 16
// baseline (speedup 1.0000x reference)
#include <cuda_runtime.h>
#include <cuda_bf16.h>
#include <math.h>
#include <stdint.h>

#define NN 4096
#define DD 256
#define LL 3
#define ND (NN * DD)
#define NTB 528   // 32*33/2 upper-triangular 128x128 tiles
#define KZ 2      // split-K slabs for thresh

// ---------------- scratch (device globals; no allocation allowed) ----------
__device__ float g_X[4][ND];
__device__ float g_H1[4][ND];
__device__ float g_Hm[4][ND];
__device__ float g_ACC[4][ND];
__device__ float g_G[4][ND];
__device__ __nv_bfloat16 g_P[4][NN * NN];     // thresholded adj {0,1}, 128 MB
__device__ float g_Yp[KZ][4][ND];
__device__ __nv_bfloat16 g_Hh[4][ND];
__device__ __nv_bfloat16 g_Hl[4][ND];
__device__ __nv_bfloat16 g_Xth[4][ND];        // X^T bf16 hi [256,4096]
__device__ __nv_bfloat16 g_Xtl[4][ND];
__device__ __nv_bfloat16 g_Wth[3][8][DD * DD];
__device__ __nv_bfloat16 g_Wtl[3][8][DD * DD];
__device__ float g_sumpart[4][64][DD];        // per-m-block column sums of H2
__device__ float g_mean[4];
__device__ float g_colpart[4][64 * 512];      // per-m-block col sum|sumsq of Hm
__device__ float g_bnscale[4][DD];
__device__ float g_bnshift[4][DD];
__device__ float g_msepart[256 * 3];
__device__ int g_ctr[2][4];                    // last-block counters (start 0)

__device__ __forceinline__ float eluf(float x) {
    return x > 0.0f ? x : (expf(x) - 1.0f);
}
__device__ __forceinline__ int wset_of(int br) {
    return (br == 0) ? 0 : (br == 2 ? 2 : 1);
}

// =================== warp MMA / async helpers ================================
__device__ __forceinline__ uint32_t smem_u32(const void* p) {
    uint32_t a;
    asm("{ .reg .u64 t; cvta.to.shared.u64 t, %1; cvt.u32.u64 %0, t; }"
        : "=r"(a) : "l"(p));
    return a;
}
__device__ __forceinline__ void ldsm4(uint32_t (&r)[4], uint32_t addr) {
    asm volatile("ldmatrix.sync.aligned.m8n8.x4.shared.b16 {%0,%1,%2,%3}, [%4];"
                 : "=r"(r[0]), "=r"(r[1]), "=r"(r[2]), "=r"(r[3]) : "r"(addr));
}
__device__ __forceinline__ void mma16816(float (&d)[4], const uint32_t (&a)[4],
                                         uint32_t b0, uint32_t b1) {
    asm volatile(
        "mma.sync.aligned.m16n8k16.row.col.f32.bf16.bf16.f32 "
        "{%0,%1,%2,%3}, {%4,%5,%6,%7}, {%8,%9}, {%0,%1,%2,%3};"
        : "+f"(d[0]), "+f"(d[1]), "+f"(d[2]), "+f"(d[3])
        : "r"(a[0]), "r"(a[1]), "r"(a[2]), "r"(a[3]), "r"(b0), "r"(b1));
}
__device__ __forceinline__ void cp16(uint32_t dst, const void* src) {
    asm volatile("cp.async.ca.shared.global [%0], [%1], 16;" :: "r"(dst), "l"(src));
}
#define CP_COMMIT() asm volatile("cp.async.commit_group;" ::: "memory")
#define CP_WAIT0()  asm volatile("cp.async.wait_group 0;" ::: "memory")

// 128B-row swizzle: tile rows of 64 bf16 (128 bytes)
__device__ __forceinline__ uint32_t swz(uint32_t row, uint32_t k) {
    uint32_t o = row * 128u + k * 2u;
    return o ^ ((o >> 3) & 0x70u);
}
__device__ __forceinline__ uint32_t bf2pack(float a, float b) {
    __nv_bfloat162 t = __floats2bfloat162_rn(a, b);
    return *reinterpret_cast<uint32_t*>(&t);
}

// ====== P = (H@H^T > mean) as bf16 {0,1}; symmetric tiles + mirror ==========
#define ADJ_SMEM 131072
__global__ __launch_bounds__(256, 1) void adj_mma()
{
    extern __shared__ __align__(16) char smem[];
    const uint32_t sb = smem_u32(smem);
    const int tid = threadIdx.x, wid = tid >> 5, lane = tid & 31;
    const int br = blockIdx.y;
    const __nv_bfloat16* Hh = g_Hh[br];
    const __nv_bfloat16* Hl = g_Hl[br];
    __nv_bfloat16* P = g_P[br];

    int b = blockIdx.x, bi = 0, rem = b;
    while (rem >= 32 - bi) { rem -= 32 - bi; ++bi; }
    const int bj = bi + rem;
    const bool diag = (bi == bj);
    const int m0 = bi * 128, n0 = bj * 128;
    const int wm = wid >> 2, wn = wid & 3;   // 2x4 warp grid, warp tile 64x32

    const uint32_t oAh = 0, oAl = 32768;
    const uint32_t oBh = diag ? 0u : 65536u, oBl = diag ? 32768u : 98304u;
    const int arow = lane & 15, akh = (lane >> 4) * 8;
    const int brow = ((lane >> 4) << 3) + (lane & 7), bkh = ((lane >> 3) & 1) * 8;

    auto issue = [&](int ch, int buf) {
        const int kb = ch * 64;
        const uint32_t bo = buf * 16384;
#pragma unroll
        for (int t = 0; t < 4; ++t) {
            int idx = tid + t * 256;
            int r = idx >> 3, g = (idx & 7) * 8;
            uint32_t so = swz(r, g);
            cp16(sb + oAh + bo + so, Hh + (m0 + r) * 256 + kb + g);
            cp16(sb + oAl + bo + so, Hl + (m0 + r) * 256 + kb + g);
            if (!diag) {
                cp16(sb + oBh + bo + so, Hh + (n0 + r) * 256 + kb + g);
                cp16(sb + oBl + bo + so, Hl + (n0 + r) * 256 + kb + g);
            }
        }
    };

    float c[4][4][4] = {};
    issue(0, 0);
    CP_COMMIT();
    int buf = 0;

    for (int ch = 0; ch < 4; ++ch) {
        CP_WAIT0();
        __syncthreads();
        if (ch < 3) { issue(ch + 1, buf ^ 1); CP_COMMIT(); }
        const uint32_t bo = buf * 16384;
#pragma unroll
        for (int s = 0; s < 4; ++s) {
            uint32_t ah[4][4], al[4][4];
#pragma unroll
            for (int mt = 0; mt < 4; ++mt) {
                ldsm4(ah[mt], sb + oAh + bo + swz(wm * 64 + mt * 16 + arow, s * 16 + akh));
                ldsm4(al[mt], sb + oAl + bo + swz(wm * 64 + mt * 16 + arow, s * 16 + akh));
            }
#pragma unroll
            for (int np = 0; np < 2; ++np) {
                uint32_t bh[4], bl[4];
                ldsm4(bh, sb + oBh + bo + swz(wn * 32 + np * 16 + brow, s * 16 + bkh));
                ldsm4(bl, sb + oBl + bo + swz(wn * 32 + np * 16 + brow, s * 16 + bkh));
#pragma unroll
                for (int mt = 0; mt < 4; ++mt) {
#pragma unroll
                    for (int j = 0; j < 2; ++j) {
                        mma16816(c[mt][np * 2 + j], ah[mt], bh[2 * j], bh[2 * j + 1]);
                        mma16816(c[mt][np * 2 + j], ah[mt], bl[2 * j], bl[2 * j + 1]);
                        mma16816(c[mt][np * 2 + j], al[mt], bh[2 * j], bh[2 * j + 1]);
                    }
                }
            }
        }
        buf ^= 1;
    }

    // threshold in registers; write upper tile
    const float mean = g_mean[br];
    const int lr = lane >> 2, lc = (lane & 3) * 2;
    float p[4][4][4];
#pragma unroll
    for (int mt = 0; mt < 4; ++mt)
#pragma unroll
        for (int nt = 0; nt < 4; ++nt) {
#pragma unroll
            for (int q = 0; q < 4; ++q)
                p[mt][nt][q] = (c[mt][nt][q] > mean) ? 1.0f : 0.0f;
            int m = m0 + wm * 64 + mt * 16 + lr;
            int n = n0 + wn * 32 + nt * 8 + lc;
            *(uint32_t*)&P[(size_t)m * NN + n] = bf2pack(p[mt][nt][0], p[mt][nt][1]);
            *(uint32_t*)&P[(size_t)(m + 8) * NN + n] = bf2pack(p[mt][nt][2], p[mt][nt][3]);
        }

    // mirror via bf16 smem transpose
    if (!diag) {
        __nv_bfloat16* T = reinterpret_cast<__nv_bfloat16*>(smem);  // [128][136]
        __syncthreads();
#pragma unroll
        for (int mt = 0; mt < 4; ++mt)
#pragma unroll
            for (int nt = 0; nt < 4; ++nt) {
                int ml = wm * 64 + mt * 16 + lr;
                int nl = wn * 32 + nt * 8 + lc;
                T[nl * 136 + ml] = __float2bfloat16(p[mt][nt][0]);
                T[(nl + 1) * 136 + ml] = __float2bfloat16(p[mt][nt][1]);
                T[nl * 136 + ml + 8] = __float2bfloat16(p[mt][nt][2]);
                T[(nl + 1) * 136 + ml + 8] = __float2bfloat16(p[mt][nt][3]);
            }
        __syncthreads();
        int n = tid >> 1, mh = (tid & 1) * 64;
        uint4* dst = reinterpret_cast<uint4*>(&P[(size_t)(n0 + n) * NN + m0 + mh]);
        const uint4* src = reinterpret_cast<const uint4*>(T + n * 136 + mh);
#pragma unroll
        for (int q = 0; q < 8; ++q) dst[q] = src[q];
    }
}

// ====== Yp[kz] = P[:, slab] @ X[slab]: cp.async A (bf16 P) and B ============
#define THR_SMEM 163840
__global__ __launch_bounds__(256, 1) void thresh_mma()
{
    extern __shared__ __align__(16) char smem[];
    const uint32_t sb = smem_u32(smem);
    const int tid = threadIdx.x, wid = tid >> 5, lane = tid & 31;
    const int m0 = blockIdx.x * 128;
    const int kz = blockIdx.y;
    const int br = blockIdx.z;
    const __nv_bfloat16* P = g_P[br];
    const __nv_bfloat16* Xth = g_Xth[br];
    const __nv_bfloat16* Xtl = g_Xtl[br];
    const int wm = wid >> 2, wn = wid & 3;   // warp tile 64m x 64n

    const uint32_t oA = 0, oBh = 32768, oBl = 98304;
    const int arow = lane & 15, akh = (lane >> 4) * 8;
    const int brow = ((lane >> 4) << 3) + (lane & 7), bkh = ((lane >> 3) & 1) * 8;

    auto issue = [&](int ch, int buf) {
        const int kb = kz * (NN / KZ) + ch * 64;
#pragma unroll
        for (int t = 0; t < 4; ++t) {
            int idx = tid + t * 256;
            int r = idx >> 3, g = (idx & 7) * 8;
            cp16(sb + oA + buf * 16384 + swz(r, g),
                 P + (size_t)(m0 + r) * NN + kb + g);
        }
#pragma unroll
        for (int t = 0; t < 8; ++t) {
            int idx = tid + t * 256;
            int r = idx >> 3, g = (idx & 7) * 8;
            uint32_t so = swz(r, g);
            cp16(sb + oBh + buf * 32768 + so, Xth + r * 4096 + kb + g);
            cp16(sb + oBl + buf * 32768 + so, Xtl + r * 4096 + kb + g);
        }
    };

    float c[4][8][4] = {};
    issue(0, 0);
    CP_COMMIT();
    int buf = 0;
    const int NCH = (NN / KZ) / 64;

    for (int ch = 0; ch < NCH; ++ch) {
        CP_WAIT0();
        __syncthreads();
        if (ch < NCH - 1) { issue(ch + 1, buf ^ 1); CP_COMMIT(); }
        const uint32_t boA = buf * 16384, boB = buf * 32768;
#pragma unroll
        for (int s = 0; s < 4; ++s) {
            uint32_t a[4][4];
#pragma unroll
            for (int mt = 0; mt < 4; ++mt)
                ldsm4(a[mt], sb + oA + boA + swz(wm * 64 + mt * 16 + arow, s * 16 + akh));
#pragma unroll
            for (int np = 0; np < 4; ++np) {
                uint32_t bh[4], bl[4];
                ldsm4(bh, sb + oBh + boB + swz(wn * 64 + np * 16 + brow, s * 16 + bkh));
                ldsm4(bl, sb + oBl + boB + swz(wn * 64 + np * 16 + brow, s * 16 + bkh));
#pragma unroll
                for (int mt = 0; mt < 4; ++mt) {
#pragma unroll
                    for (int j = 0; j < 2; ++j) {
                        mma16816(c[mt][np * 2 + j], a[mt], bh[2 * j], bh[2 * j + 1]);
                        mma16816(c[mt][np * 2 + j], a[mt], bl[2 * j], bl[2 * j + 1]);
                    }
                }
            }
        }
        buf ^= 1;
    }

    float* Yp = g_Yp[kz][br];
    const int lr = lane >> 2, lc = (lane & 3) * 2;
#pragma unroll
    for (int mt = 0; mt < 4; ++mt)
#pragma unroll
        for (int nt = 0; nt < 8; ++nt) {
            int m = m0 + wm * 64 + mt * 16 + lr;
            int n = wn * 64 + nt * 8 + lc;
            *(float2*)&Yp[m * 256 + n] = make_float2(c[mt][nt][0], c[mt][nt][1]);
            *(float2*)&Yp[(m + 8) * 256 + n] = make_float2(c[mt][nt][2], c[mt][nt][3]);
        }
}

// ========== small GEMM via mma.sync, batched over 4 branches ================
// AY: A := X + (Yp0 + Yp1)  (fused combine_Y, identical arithmetic order)
// XT: epilogue also emits X^T bf16 hi/lo (fused xt_split, identical values)
// CS: 1 = colsum partials + last-block mean; 2 = colstats + last-block BN
#define SM_SMEM 81920
template <int ABN, int EPI, int AY, int XT, int CS>
__global__ __launch_bounds__(256, 1) void gemm_mma(
    const float* __restrict__ a0, const float* __restrict__ a1,
    const float* __restrict__ a2, const float* __restrict__ a3, int mat,
    const float* __restrict__ b0, const float* __restrict__ b1,
    const float* __restrict__ b2, const float* __restrict__ b3,
    const float* __restrict__ gb0, const float* __restrict__ gb1,
    const float* __restrict__ gb2, const float* __restrict__ gb3)
{
    extern __shared__ __align__(16) char smem[];
    const uint32_t sb = smem_u32(smem);
    const int tid = threadIdx.x, wid = tid >> 5, lane = tid & 31;
    const int n0 = blockIdx.x * 128, m0 = blockIdx.y * 64;
    const int br = blockIdx.z;
    const float* As4[4] = {a0, a1, a2, a3};
    const float* Bs4[4] = {b0, b1, b2, b3};
    const float* Gs4[4] = {gb0, gb1, gb2, gb3};
    const float* A = As4[br];
    const float* bias = Bs4[br];
    const float* Yp0 = g_Yp[0][br];
    const float* Yp1 = g_Yp[1][br];
    const int ws = wset_of(br);
    const __nv_bfloat16* Wth = g_Wth[ws][mat];
    const __nv_bfloat16* Wtl = g_Wtl[ws][mat];
    const int wm = wid >> 2, wn = wid & 3;   // warp tile 32m x 32n

    const uint32_t oAh = 0, oAl = 8192, oBh = 16384, oBl = 49152;
    const int arow = lane & 15, akh = (lane >> 4) * 8;
    const int brow = ((lane >> 4) << 3) + (lane & 7), bkh = ((lane >> 3) & 1) * 8;

    auto issueB = [&](int ch, int buf) {
        const int kb = ch * 64;
        const uint32_t bo = buf * 16384;
#pragma unroll
        for (int t = 0; t < 4; ++t) {
            int idx = tid + t * 256;
            int r = idx >> 3, g = (idx & 7) * 8;
            uint32_t so = swz(r, g);
            cp16(sb + oBh + bo + so, Wth + (n0 + r) * 256 + kb + g);
            cp16(sb + oBl + bo + so, Wtl + (n0 + r) * 256 + kb + g);
        }
    };
    auto loadA = [&](int ch) {
        const int kb = ch * 64;
#pragma unroll
        for (int t = 0; t < 2; ++t) {
            int idx = tid + t * 256;
            int r = idx >> 3, g = (idx & 7) * 8;
            const size_t off = (size_t)(m0 + r) * 256 + kb + g;
            float v[8];
            *(float4*)&v[0] = *(const float4*)(A + off);
            *(float4*)&v[4] = *(const float4*)(A + off + 4);
            if (AY) {
                float p0[8], p1[8];
                *(float4*)&p0[0] = *(const float4*)(Yp0 + off);
                *(float4*)&p0[4] = *(const float4*)(Yp0 + off + 4);
                *(float4*)&p1[0] = *(const float4*)(Yp1 + off);
                *(float4*)&p1[4] = *(const float4*)(Yp1 + off + 4);
#pragma unroll
                for (int j = 0; j < 8; ++j) v[j] = v[j] + (p0[j] + p1[j]);
            }
            if (ABN) {
                float4 s0 = *(const float4*)&g_bnscale[br][kb + g];
                float4 s1 = *(const float4*)&g_bnscale[br][kb + g + 4];
                float4 h0 = *(const float4*)&g_bnshift[br][kb + g];
                float4 h1 = *(const float4*)&g_bnshift[br][kb + g + 4];
                float sc[8] = {s0.x, s0.y, s0.z, s0.w, s1.x, s1.y, s1.z, s1.w};
                float sh[8] = {h0.x, h0.y, h0.z, h0.w, h1.x, h1.y, h1.z, h1.w};
#pragma unroll
                for (int j = 0; j < 8; ++j) v[j] = fmaxf(v[j] * sc[j] + sh[j], 0.0f);
            }
            float hi[8], lo[8];
#pragma unroll
            for (int j = 0; j < 8; ++j) {
                hi[j] = __bfloat162float(__float2bfloat16(v[j]));
                lo[j] = v[j] - hi[j];
            }
            *(uint4*)(smem + oAh + swz(r, g)) =
                make_uint4(bf2pack(hi[0], hi[1]), bf2pack(hi[2], hi[3]),
                           bf2pack(hi[4], hi[5]), bf2pack(hi[6], hi[7]));
            *(uint4*)(smem + oAl + swz(r, g)) =
                make_uint4(bf2pack(lo[0], lo[1]), bf2pack(lo[2], lo[3]),
                           bf2pack(lo[4], lo[5]), bf2pack(lo[6], lo[7]));
        }
    };

    float c[2][4][4] = {};
    issueB(0, 0);
    CP_COMMIT();
    int buf = 0;

    for (int ch = 0; ch < 4; ++ch) {
        CP_WAIT0();
        __syncthreads();
        if (ch < 3) { issueB(ch + 1, buf ^ 1); CP_COMMIT(); }
        loadA(ch);
        __syncthreads();
        const uint32_t boB = buf * 16384;
#pragma unroll
        for (int s = 0; s < 4; ++s) {
            uint32_t ah[2][4], al[2][4];
#pragma unroll
            for (int mt = 0; mt < 2; ++mt) {
                ldsm4(ah[mt], sb + oAh + swz(wm * 32 + mt * 16 + arow, s * 16 + akh));
                ldsm4(al[mt], sb + oAl + swz(wm * 32 + mt * 16 + arow, s * 16 + akh));
            }
#pragma unroll
            for (int np = 0; np < 2; ++np) {
                uint32_t bh[4], bl[4];
                ldsm4(bh, sb + oBh + boB + swz(wn * 32 + np * 16 + brow, s * 16 + bkh));
                ldsm4(bl, sb + oBl + boB + swz(wn * 32 + np * 16 + brow, s * 16 + bkh));
#pragma unroll
                for (int mt = 0; mt < 2; ++mt) {
#pragma unroll
                    for (int j = 0; j < 2; ++j) {
                        mma16816(c[mt][np * 2 + j], ah[mt], bh[2 * j], bh[2 * j + 1]);
                        mma16816(c[mt][np * 2 + j], ah[mt], bl[2 * j], bl[2 * j + 1]);
                        mma16816(c[mt][np * 2 + j], al[mt], bh[2 * j], bh[2 * j + 1]);
                    }
                }
            }
        }
        buf ^= 1;
    }

    // epilogue smem reuse: XT transpose buffers OR CS staging buffer [64][132]
    __nv_bfloat16* Th = reinterpret_cast<__nv_bfloat16*>(smem);        // [128][72]
    __nv_bfloat16* Tl = Th + 128 * 72;
    float* SV = reinterpret_cast<float*>(smem);                        // [64][132]
    if (XT || CS) __syncthreads();   // mainloop smem no longer needed

    const int lr = lane >> 2, lc = (lane & 3) * 2;
#pragma unroll
    for (int mt = 0; mt < 2; ++mt)
#pragma unroll
        for (int nt = 0; nt < 4; ++nt) {
            const int n = n0 + wn * 32 + nt * 8 + lc;
            float2 bv = *(const float2*)&bias[n];
#pragma unroll
            for (int h = 0; h < 2; ++h) {
                const int m = m0 + wm * 32 + mt * 16 + lr + h * 8;
                const int lm = m - m0;                 // 0..63
                const int ln = wn * 32 + nt * 8 + lc;  // 0..127
                float v0 = c[mt][nt][h * 2 + 0] + bv.x;
                float v1 = c[mt][nt][h * 2 + 1] + bv.y;
                if (EPI == 0 || EPI == 2) { v0 = eluf(v0); v1 = eluf(v1); }
                if (EPI == 0) {
                    *(float2*)&g_H1[br][m * 256 + n] = make_float2(v0, v1);
                } else if (EPI == 1) {
                    *(float2*)&g_Hm[br][m * 256 + n] = make_float2(v0, v1);
                    if (CS == 2) {
                        SV[lm * 132 + ln] = v0;
                        SV[lm * 132 + ln + 1] = v1;
                    }
                } else if (EPI == 2) {
                    float h0 = __bfloat162float(__float2bfloat16(v0));
                    float h1 = __bfloat162float(__float2bfloat16(v1));
                    float l0 = __bfloat162float(__float2bfloat16(v0 - h0));
                    float l1 = __bfloat162float(__float2bfloat16(v1 - h1));
                    *(uint32_t*)&g_Hh[br][m * 256 + n] = bf2pack(h0, h1);
                    *(uint32_t*)&g_Hl[br][m * 256 + n] = bf2pack(v0 - h0, v1 - h1);
                    if (CS == 1) {
                        SV[lm * 132 + ln] = h0 + l0;
                        SV[lm * 132 + ln + 1] = h1 + l1;
                    }
                } else if (EPI == 5) {
                    float2 ac = *(const float2*)&g_ACC[br][m * 256 + n];
                    *(float2*)&g_G[br][m * 256 + n] =
                        make_float2((ac.x + v0) * (1.0f / 3.0f),
                                    (ac.y + v1) * (1.0f / 3.0f));
                } else {
                    *(float2*)&g_X[br][m * 256 + n] = make_float2(v0, v1);
                    if (EPI == 3)
                        *(float2*)&g_ACC[br][m * 256 + n] = make_float2(v0, v1);
                    if (EPI == 4) {
                        float2 ac = *(const float2*)&g_ACC[br][m * 256 + n];
                        *(float2*)&g_ACC[br][m * 256 + n] =
                            make_float2(ac.x + v0, ac.y + v1);
                    }
                    if (XT) {
                        __nv_bfloat16 h0 = __float2bfloat16(v0);
                        __nv_bfloat16 h1 = __float2bfloat16(v1);
                        Th[ln * 72 + lm] = h0;
                        Th[(ln + 1) * 72 + lm] = h1;
                        Tl[ln * 72 + lm] = __float2bfloat16(v0 - __bfloat162float(h0));
                        Tl[(ln + 1) * 72 + lm] = __float2bfloat16(v1 - __bfloat162float(h1));
                    }
                }
            }
        }

    if (XT) {
        __syncthreads();
        const int row = tid & 127;
        const bool lo = tid >= 128;
        const __nv_bfloat16* src = (lo ? Tl : Th) + row * 72;
        __nv_bfloat16* dst = (lo ? g_Xtl[br] : g_Xth[br]) + (n0 + row) * 4096 + m0;
#pragma unroll
        for (int q = 0; q < 8; ++q)
            reinterpret_cast<uint4*>(dst)[q] =
                reinterpret_cast<const uint4*>(src)[q];
    }
    if (CS) {
        __syncthreads();
        if (tid < 128) {
            float s = 0.0f, q = 0.0f;
            for (int mm = 0; mm < 64; ++mm) {
                float v = SV[mm * 132 + tid];
                s += v;
                if (CS == 2) q += v * v;
            }
            if (CS == 1) {
                g_sumpart[br][blockIdx.y][n0 + tid] = s;
            } else {
                g_colpart[br][blockIdx.y * 512 + n0 + tid] = s;
                g_colpart[br][blockIdx.y * 512 + 256 + n0 + tid] = q;
            }
        }
        // last block per branch does the final reduction in-kernel
        __threadfence();
        __syncthreads();
        __shared__ int s_last;
        if (tid == 0)
            s_last = (atomicAdd(&g_ctr[CS - 1][br], 1) == 127) ? 1 : 0;
        __syncthreads();
        if (s_last) {
            if (CS == 1) {
                // mean = ||colsum||^2 / N^2 (same order as old colsum_mean)
                float s = 0.0f;
                for (int b2 = 0; b2 < 64; ++b2) s += g_sumpart[br][b2][tid];
                float* red = SV;   // reuse smem
                red[tid] = s * s;
                __syncthreads();
                for (int o = 128; o > 0; o >>= 1) {
                    if (tid < o) red[tid] += red[tid + o];
                    __syncthreads();
                }
                if (tid == 0) {
                    g_mean[br] = red[0] * (1.0f / ((float)NN * (float)NN));
                    g_ctr[0][br] = 0;
                    __threadfence();
                }
            } else {
                const float* gamma = Gs4[br];
                const float* beta = gamma + 256;
                float s = 0.0f, q = 0.0f;
                for (int b2 = 0; b2 < 64; ++b2) {
                    s += g_colpart[br][b2 * 512 + tid];
                    q += g_colpart[br][b2 * 512 + 256 + tid];
                }
                float mu = s * (1.0f / (float)NN);
                float var = q * (1.0f / (float)NN) - mu * mu;
                float rstd = rsqrtf(var + 1e-5f);
                float sc = gamma[tid] * rstd;
                g_bnscale[br][tid] = sc;
                g_bnshift[br][tid] = beta[tid] - mu * sc;
                __syncthreads();
                if (tid == 0) {
                    g_ctr[1][br] = 0;
                    __threadfence();
                }
            }
        }
    }
}

// =============== weight transpose + bf16 split (3 sets x 8 mats) ============
__global__ void wt_split(const float* __restrict__ aw0, const float* __restrict__ aw1,
                         const float* __restrict__ aw2, const float* __restrict__ mw0,
                         const float* __restrict__ mw1, const float* __restrict__ mw2)
{
    const int z = blockIdx.z, ws = z >> 3, mat = z & 7;
    const float* aws[3] = {aw0, aw1, aw2};
    const float* mws[3] = {mw0, mw1, mw2};
    const float* src = (mat < 2) ? aws[ws] + mat * 65536 : mws[ws] + (mat - 2) * 65536;
    __shared__ float t[32][33];
    const int r0 = blockIdx.x * 32, c0 = blockIdx.y * 32;
    const int x = threadIdx.x, y = threadIdx.y;
    for (int i = 0; i < 32; i += 8)
        t[y + i][x] = src[(r0 + y + i) * 256 + c0 + x];
    __syncthreads();
    for (int i = 0; i < 32; i += 8) {
        float v = t[x][y + i];
        __nv_bfloat16 h = __float2bfloat16(v);
        float hf = __bfloat162float(h);
        g_Wth[ws][mat][(c0 + y + i) * 256 + r0 + x] = h;
        g_Wtl[ws][mat][(c0 + y + i) * 256 + r0 + x] = __float2bfloat16(v - hf);
    }
}

// =============== X transpose + bf16 split, batched (layer 0 only) ===========
__global__ void xt_split(const float* __restrict__ x0, const float* __restrict__ x1,
                         const float* __restrict__ x2, const float* __restrict__ x3)
{
    const int br = blockIdx.z;
    const float* Xs[4] = {x0, x1, x2, x3};
    const float* X = Xs[br];
    __shared__ float t[32][33];
    const int r0 = blockIdx.x * 32, c0 = blockIdx.y * 32;
    const int x = threadIdx.x, y = threadIdx.y;
    for (int i = 0; i < 32; i += 8)
        t[y + i][x] = X[(r0 + y + i) * 256 + c0 + x];
    __syncthreads();
    for (int i = 0; i < 32; i += 8) {
        float v = t[x][y + i];
        __nv_bfloat16 h = __float2bfloat16(v);
        float hf = __bfloat162float(h);
        g_Xth[br][(c0 + y + i) * 4096 + r0 + x] = h;
        g_Xtl[br][(c0 + y + i) * 4096 + r0 + x] = __float2bfloat16(v - hf);
    }
}

// ---------------- MSE --------------------------------------------------------
__global__ void mse_partial()
{
    int t = threadIdx.x, b = blockIdx.x;
    float s0 = 0.0f, s1 = 0.0f, s2 = 0.0f;
    for (int i = b * 256 + t; i < ND; i += 256 * 256) {
        float ga = g_G[3][i];
        float d0 = g_G[0][i] - ga;
        float d1 = g_G[1][i] - ga;
        float d2 = g_G[2][i] - ga;
        s0 += d0 * d0;
        s1 += d1 * d1;
        s2 += d2 * d2;
    }
    __shared__ float r[3][256];
    r[0][t] = s0; r[1][t] = s1; r[2][t] = s2;
    __syncthreads();
    for (int o = 128; o > 0; o >>= 1) {
        if (t < o) {
            r[0][t] += r[0][t + o];
            r[1][t] += r[1][t + o];
            r[2][t] += r[2][t + o];
        }
        __syncthreads();
    }
    if (t == 0) {
        g_msepart[b * 3 + 0] = r[0][0];
        g_msepart[b * 3 + 1] = r[1][0];
        g_msepart[b * 3 + 2] = r[2][0];
    }
}

__global__ void mse_final(float* __restrict__ out)
{
    int t = threadIdx.x;
    __shared__ float r[256];
    for (int v = 0; v < 3; ++v) {
        r[t] = g_msepart[t * 3 + v];
        __syncthreads();
        for (int o = 128; o > 0; o >>= 1) {
            if (t < o) r[t] += r[t + o];
            __syncthreads();
        }
        if (t == 0) out[v] = r[0] * (1.0f / (float)ND);
        __syncthreads();
    }
}

// ---------------- host driver ------------------------------------------------
extern "C" void kernel_launch(void* const* d_in, const int* in_sizes, int n_in,
                              void* d_out, int out_size)
{
    const float* QV = (const float*)d_in[0];
    const float* Q  = (const float*)d_in[1];
    const float* V  = (const float*)d_in[2];
    const float* A  = (const float*)d_in[3];
    const float* adjW_qv  = (const float*)d_in[4];
    const float* adjb_qv  = (const float*)d_in[5];
    const float* mlpW_qv  = (const float*)d_in[6];
    const float* mlpb_qv  = (const float*)d_in[7];
    const float* mlpbn_qv = (const float*)d_in[8];
    const float* adjW_t   = (const float*)d_in[9];
    const float* adjb_t   = (const float*)d_in[10];
    const float* mlpW_t   = (const float*)d_in[11];
    const float* mlpb_t   = (const float*)d_in[12];
    const float* mlpbn_t  = (const float*)d_in[13];
    const float* adjW_v   = (const float*)d_in[14];
    const float* adjb_v   = (const float*)d_in[15];
    const float* mlpW_v   = (const float*)d_in[16];
    const float* mlpb_v   = (const float*)d_in[17];
    const float* mlpbn_v  = (const float*)d_in[18];

    cudaFuncSetAttribute(adj_mma, cudaFuncAttributeMaxDynamicSharedMemorySize, ADJ_SMEM);
    cudaFuncSetAttribute(thresh_mma, cudaFuncAttributeMaxDynamicSharedMemorySize, THR_SMEM);
    cudaFuncSetAttribute(gemm_mma<0, 0, 0, 0, 0>, cudaFuncAttributeMaxDynamicSharedMemorySize, SM_SMEM);
    cudaFuncSetAttribute(gemm_mma<0, 1, 1, 0, 2>, cudaFuncAttributeMaxDynamicSharedMemorySize, SM_SMEM);
    cudaFuncSetAttribute(gemm_mma<0, 2, 0, 0, 1>, cudaFuncAttributeMaxDynamicSharedMemorySize, SM_SMEM);
    cudaFuncSetAttribute(gemm_mma<1, 3, 0, 1, 0>, cudaFuncAttributeMaxDynamicSharedMemorySize, SM_SMEM);
    cudaFuncSetAttribute(gemm_mma<1, 4, 0, 1, 0>, cudaFuncAttributeMaxDynamicSharedMemorySize, SM_SMEM);
    cudaFuncSetAttribute(gemm_mma<1, 5, 0, 0, 0>, cudaFuncAttributeMaxDynamicSharedMemorySize, SM_SMEM);

    float *pX, *pH1, *pHm;
    cudaGetSymbolAddress((void**)&pX, g_X);
    cudaGetSymbolAddress((void**)&pH1, g_H1);
    cudaGetSymbolAddress((void**)&pHm, g_Hm);

    const float* ab[4] = {adjb_qv, adjb_t, adjb_v, adjb_t};
    const float* mb[4] = {mlpb_qv, mlpb_t, mlpb_v, mlpb_t};
    const float* bn[4] = {mlpbn_qv, mlpbn_t, mlpbn_v, mlpbn_t};

    wt_split<<<dim3(8, 8, 24), dim3(32, 8)>>>(adjW_qv, adjW_t, adjW_v,
                                              mlpW_qv, mlpW_t, mlpW_v);

    const dim3 g_sm(2, 64, 4);
    for (int l = 0; l < LL; ++l) {
        const float* X0 = (l == 0) ? QV : pX;
        const float* X1 = (l == 0) ? Q : pX + (size_t)ND;
        const float* X2 = (l == 0) ? V : pX + 2 * (size_t)ND;
        const float* X3 = (l == 0) ? A : pX + 3 * (size_t)ND;

        gemm_mma<0, 0, 0, 0, 0><<<g_sm, 256, SM_SMEM>>>(
            X0, X1, X2, X3, 0, ab[0], ab[1], ab[2], ab[3],
            nullptr, nullptr, nullptr, nullptr);
        // emits Hh/Hl + colsum partials + last-block mean (no extra launches)
        gemm_mma<0, 2, 0, 0, 1><<<g_sm, 256, SM_SMEM>>>(
            pH1, pH1 + (size_t)ND, pH1 + 2 * (size_t)ND, pH1 + 3 * (size_t)ND, 1,
            ab[0] + 256, ab[1] + 256, ab[2] + 256, ab[3] + 256,
            nullptr, nullptr, nullptr, nullptr);
        adj_mma<<<dim3(NTB, 4), 256, ADJ_SMEM>>>();
        if (l == 0)   // layers 1..2 get X^T from the previous gemm's epilogue
            xt_split<<<dim3(128, 8, 4), dim3(32, 8)>>>(X0, X1, X2, X3);
        thresh_mma<<<dim3(32, KZ, 4), 256, THR_SMEM>>>();

        // MLP GEMM 1: fused Y-combine + colstats + last-block BN finalize
        gemm_mma<0, 1, 1, 0, 2><<<g_sm, 256, SM_SMEM>>>(
            X0, X1, X2, X3, 2 + 2 * l,
            mb[0] + l * 512, mb[1] + l * 512, mb[2] + l * 512, mb[3] + l * 512,
            bn[0] + l * 512, bn[1] + l * 512, bn[2] + l * 512, bn[3] + l * 512);
        const float* c0 = mb[0] + l * 512 + 256;
        const float* c1 = mb[1] + l * 512 + 256;
        const float* c2 = mb[2] + l * 512 + 256;
        const float* c3 = mb[3] + l * 512 + 256;
        if (l == 0)
            gemm_mma<1, 3, 0, 1, 0><<<g_sm, 256, SM_SMEM>>>(
                pHm, pHm + (size_t)ND, pHm + 2 * (size_t)ND, pHm + 3 * (size_t)ND,
                3 + 2 * l, c0, c1, c2, c3, nullptr, nullptr, nullptr, nullptr);
        else if (l == 1)
            gemm_mma<1, 4, 0, 1, 0><<<g_sm, 256, SM_SMEM>>>(
                pHm, pHm + (size_t)ND, pHm + 2 * (size_t)ND, pHm + 3 * (size_t)ND,
                3 + 2 * l, c0, c1, c2, c3, nullptr, nullptr, nullptr, nullptr);
        else
            gemm_mma<1, 5, 0, 0, 0><<<g_sm, 256, SM_SMEM>>>(
                pHm, pHm + (size_t)ND, pHm + 2 * (size_t)ND, pHm + 3 * (size_t)ND,
                3 + 2 * l, c0, c1, c2, c3, nullptr, nullptr, nullptr, nullptr);
    }

    mse_partial<<<256, 256>>>();
    mse_final<<<1, 256>>>((float*)d_out);
}

// round 17
// speedup vs baseline: 1.0667x; 1.0667x over previous
#include <cuda_runtime.h>
#include <cuda_bf16.h>
#include <math.h>
#include <stdint.h>

#define NN 4096
#define DD 256
#define LL 3
#define ND (NN * DD)
#define NTB 528   // 32*33/2 upper-triangular 128x128 tiles
#define KZ 2      // split-K slabs for thresh

// ---------------- scratch (device globals; no allocation allowed) ----------
__device__ float g_X[4][ND];
__device__ float g_H1[4][ND];
__device__ float g_Hm[4][ND];
__device__ float g_ACC[4][ND];
__device__ float g_G[4][ND];
__device__ __nv_bfloat16 g_P[4][NN * NN];     // thresholded adj {0,1}, 128 MB
__device__ float g_Yp[KZ][4][ND];
__device__ __nv_bfloat16 g_Hh[4][ND];
__device__ __nv_bfloat16 g_Hl[4][ND];
__device__ __nv_bfloat16 g_Xth[4][ND];        // X^T bf16 hi [256,4096]
__device__ __nv_bfloat16 g_Xtl[4][ND];
__device__ __nv_bfloat16 g_Wth[3][8][DD * DD];
__device__ __nv_bfloat16 g_Wtl[3][8][DD * DD];
__device__ float g_sumpart[4][64][DD];        // per-m-block column sums of H2
__device__ float g_mean[4];
__device__ float g_colpart[4][64 * 512];      // per-m-block col sum|sumsq of Hm
__device__ float g_bnscale[4][DD];
__device__ float g_bnshift[4][DD];
__device__ float g_msepart[256 * 3];

__device__ __forceinline__ float eluf(float x) {
    return x > 0.0f ? x : (expf(x) - 1.0f);
}
__device__ __forceinline__ int wset_of(int br) {
    return (br == 0) ? 0 : (br == 2 ? 2 : 1);
}

// =================== warp MMA / async helpers ================================
__device__ __forceinline__ uint32_t smem_u32(const void* p) {
    uint32_t a;
    asm("{ .reg .u64 t; cvta.to.shared.u64 t, %1; cvt.u32.u64 %0, t; }"
        : "=r"(a) : "l"(p));
    return a;
}
__device__ __forceinline__ void ldsm4(uint32_t (&r)[4], uint32_t addr) {
    asm volatile("ldmatrix.sync.aligned.m8n8.x4.shared.b16 {%0,%1,%2,%3}, [%4];"
                 : "=r"(r[0]), "=r"(r[1]), "=r"(r[2]), "=r"(r[3]) : "r"(addr));
}
__device__ __forceinline__ void mma16816(float (&d)[4], const uint32_t (&a)[4],
                                         uint32_t b0, uint32_t b1) {
    asm volatile(
        "mma.sync.aligned.m16n8k16.row.col.f32.bf16.bf16.f32 "
        "{%0,%1,%2,%3}, {%4,%5,%6,%7}, {%8,%9}, {%0,%1,%2,%3};"
        : "+f"(d[0]), "+f"(d[1]), "+f"(d[2]), "+f"(d[3])
        : "r"(a[0]), "r"(a[1]), "r"(a[2]), "r"(a[3]), "r"(b0), "r"(b1));
}
// .cg: L2-only fill — cp.async data is consumed via ldmatrix from smem and
// never re-read through L1, so L1 allocation is pure L1TEX pollution.
__device__ __forceinline__ void cp16(uint32_t dst, const void* src) {
    asm volatile("cp.async.cg.shared.global [%0], [%1], 16;" :: "r"(dst), "l"(src));
}
#define CP_COMMIT() asm volatile("cp.async.commit_group;" ::: "memory")
#define CP_WAIT0()  asm volatile("cp.async.wait_group 0;" ::: "memory")

// 128B-row swizzle: tile rows of 64 bf16 (128 bytes)
__device__ __forceinline__ uint32_t swz(uint32_t row, uint32_t k) {
    uint32_t o = row * 128u + k * 2u;
    return o ^ ((o >> 3) & 0x70u);
}
__device__ __forceinline__ uint32_t bf2pack(float a, float b) {
    __nv_bfloat162 t = __floats2bfloat162_rn(a, b);
    return *reinterpret_cast<uint32_t*>(&t);
}

// ====== mean of H@H^T via column-sum identity: ||colsum||^2/N^2 =============
__global__ void colsum_mean()
{
    const int br = blockIdx.x, t = threadIdx.x;
    float s = 0.0f;
    for (int b = 0; b < 64; ++b) s += g_sumpart[br][b][t];
    __shared__ float red[256];
    red[t] = s * s;
    __syncthreads();
    for (int o = 128; o > 0; o >>= 1) {
        if (t < o) red[t] += red[t + o];
        __syncthreads();
    }
    if (t == 0) g_mean[br] = red[0] * (1.0f / ((float)NN * (float)NN));
}

// ====== P = (H@H^T > mean) as bf16 {0,1}; symmetric tiles + mirror ==========
#define ADJ_SMEM 131072
__global__ __launch_bounds__(256, 1) void adj_mma()
{
    extern __shared__ __align__(16) char smem[];
    const uint32_t sb = smem_u32(smem);
    const int tid = threadIdx.x, wid = tid >> 5, lane = tid & 31;
    const int br = blockIdx.y;
    const __nv_bfloat16* Hh = g_Hh[br];
    const __nv_bfloat16* Hl = g_Hl[br];
    __nv_bfloat16* P = g_P[br];

    int b = blockIdx.x, bi = 0, rem = b;
    while (rem >= 32 - bi) { rem -= 32 - bi; ++bi; }
    const int bj = bi + rem;
    const bool diag = (bi == bj);
    const int m0 = bi * 128, n0 = bj * 128;
    const int wm = wid >> 2, wn = wid & 3;   // 2x4 warp grid, warp tile 64x32

    const uint32_t oAh = 0, oAl = 32768;
    const uint32_t oBh = diag ? 0u : 65536u, oBl = diag ? 32768u : 98304u;
    const int arow = lane & 15, akh = (lane >> 4) * 8;
    const int brow = ((lane >> 4) << 3) + (lane & 7), bkh = ((lane >> 3) & 1) * 8;

    auto issue = [&](int ch, int buf) {
        const int kb = ch * 64;
        const uint32_t bo = buf * 16384;
#pragma unroll
        for (int t = 0; t < 4; ++t) {
            int idx = tid + t * 256;
            int r = idx >> 3, g = (idx & 7) * 8;
            uint32_t so = swz(r, g);
            cp16(sb + oAh + bo + so, Hh + (m0 + r) * 256 + kb + g);
            cp16(sb + oAl + bo + so, Hl + (m0 + r) * 256 + kb + g);
            if (!diag) {
                cp16(sb + oBh + bo + so, Hh + (n0 + r) * 256 + kb + g);
                cp16(sb + oBl + bo + so, Hl + (n0 + r) * 256 + kb + g);
            }
        }
    };

    float c[4][4][4] = {};
    issue(0, 0);
    CP_COMMIT();
    int buf = 0;

    for (int ch = 0; ch < 4; ++ch) {
        CP_WAIT0();
        __syncthreads();
        if (ch < 3) { issue(ch + 1, buf ^ 1); CP_COMMIT(); }
        const uint32_t bo = buf * 16384;
#pragma unroll
        for (int s = 0; s < 4; ++s) {
            uint32_t ah[4][4], al[4][4];
#pragma unroll
            for (int mt = 0; mt < 4; ++mt) {
                ldsm4(ah[mt], sb + oAh + bo + swz(wm * 64 + mt * 16 + arow, s * 16 + akh));
                ldsm4(al[mt], sb + oAl + bo + swz(wm * 64 + mt * 16 + arow, s * 16 + akh));
            }
#pragma unroll
            for (int np = 0; np < 2; ++np) {
                uint32_t bh[4], bl[4];
                ldsm4(bh, sb + oBh + bo + swz(wn * 32 + np * 16 + brow, s * 16 + bkh));
                ldsm4(bl, sb + oBl + bo + swz(wn * 32 + np * 16 + brow, s * 16 + bkh));
#pragma unroll
                for (int mt = 0; mt < 4; ++mt) {
#pragma unroll
                    for (int j = 0; j < 2; ++j) {
                        mma16816(c[mt][np * 2 + j], ah[mt], bh[2 * j], bh[2 * j + 1]);
                        mma16816(c[mt][np * 2 + j], ah[mt], bl[2 * j], bl[2 * j + 1]);
                        mma16816(c[mt][np * 2 + j], al[mt], bh[2 * j], bh[2 * j + 1]);
                    }
                }
            }
        }
        buf ^= 1;
    }

    // threshold in registers; write upper tile
    const float mean = g_mean[br];
    const int lr = lane >> 2, lc = (lane & 3) * 2;
    float p[4][4][4];
#pragma unroll
    for (int mt = 0; mt < 4; ++mt)
#pragma unroll
        for (int nt = 0; nt < 4; ++nt) {
#pragma unroll
            for (int q = 0; q < 4; ++q)
                p[mt][nt][q] = (c[mt][nt][q] > mean) ? 1.0f : 0.0f;
            int m = m0 + wm * 64 + mt * 16 + lr;
            int n = n0 + wn * 32 + nt * 8 + lc;
            *(uint32_t*)&P[(size_t)m * NN + n] = bf2pack(p[mt][nt][0], p[mt][nt][1]);
            *(uint32_t*)&P[(size_t)(m + 8) * NN + n] = bf2pack(p[mt][nt][2], p[mt][nt][3]);
        }

    // mirror via bf16 smem transpose
    if (!diag) {
        __nv_bfloat16* T = reinterpret_cast<__nv_bfloat16*>(smem);  // [128][136]
        __syncthreads();
#pragma unroll
        for (int mt = 0; mt < 4; ++mt)
#pragma unroll
            for (int nt = 0; nt < 4; ++nt) {
                int ml = wm * 64 + mt * 16 + lr;
                int nl = wn * 32 + nt * 8 + lc;
                T[nl * 136 + ml] = __float2bfloat16(p[mt][nt][0]);
                T[(nl + 1) * 136 + ml] = __float2bfloat16(p[mt][nt][1]);
                T[nl * 136 + ml + 8] = __float2bfloat16(p[mt][nt][2]);
                T[(nl + 1) * 136 + ml + 8] = __float2bfloat16(p[mt][nt][3]);
            }
        __syncthreads();
        int n = tid >> 1, mh = (tid & 1) * 64;
        uint4* dst = reinterpret_cast<uint4*>(&P[(size_t)(n0 + n) * NN + m0 + mh]);
        const uint4* src = reinterpret_cast<const uint4*>(T + n * 136 + mh);
#pragma unroll
        for (int q = 0; q < 8; ++q) dst[q] = src[q];
    }
}

// ====== Yp[kz] = P[:, slab] @ X[slab]: cp.async A (bf16 P) and B ============
#define THR_SMEM 163840
__global__ __launch_bounds__(256, 1) void thresh_mma()
{
    extern __shared__ __align__(16) char smem[];
    const uint32_t sb = smem_u32(smem);
    const int tid = threadIdx.x, wid = tid >> 5, lane = tid & 31;
    const int m0 = blockIdx.x * 128;
    const int kz = blockIdx.y;
    const int br = blockIdx.z;
    const __nv_bfloat16* P = g_P[br];
    const __nv_bfloat16* Xth = g_Xth[br];
    const __nv_bfloat16* Xtl = g_Xtl[br];
    const int wm = wid >> 2, wn = wid & 3;   // warp tile 64m x 64n

    const uint32_t oA = 0, oBh = 32768, oBl = 98304;
    const int arow = lane & 15, akh = (lane >> 4) * 8;
    const int brow = ((lane >> 4) << 3) + (lane & 7), bkh = ((lane >> 3) & 1) * 8;

    auto issue = [&](int ch, int buf) {
        const int kb = kz * (NN / KZ) + ch * 64;
#pragma unroll
        for (int t = 0; t < 4; ++t) {
            int idx = tid + t * 256;
            int r = idx >> 3, g = (idx & 7) * 8;
            cp16(sb + oA + buf * 16384 + swz(r, g),
                 P + (size_t)(m0 + r) * NN + kb + g);
        }
#pragma unroll
        for (int t = 0; t < 8; ++t) {
            int idx = tid + t * 256;
            int r = idx >> 3, g = (idx & 7) * 8;
            uint32_t so = swz(r, g);
            cp16(sb + oBh + buf * 32768 + so, Xth + r * 4096 + kb + g);
            cp16(sb + oBl + buf * 32768 + so, Xtl + r * 4096 + kb + g);
        }
    };

    float c[4][8][4] = {};
    issue(0, 0);
    CP_COMMIT();
    int buf = 0;
    const int NCH = (NN / KZ) / 64;

    for (int ch = 0; ch < NCH; ++ch) {
        CP_WAIT0();
        __syncthreads();
        if (ch < NCH - 1) { issue(ch + 1, buf ^ 1); CP_COMMIT(); }
        const uint32_t boA = buf * 16384, boB = buf * 32768;
#pragma unroll
        for (int s = 0; s < 4; ++s) {
            uint32_t a[4][4];
#pragma unroll
            for (int mt = 0; mt < 4; ++mt)
                ldsm4(a[mt], sb + oA + boA + swz(wm * 64 + mt * 16 + arow, s * 16 + akh));
#pragma unroll
            for (int np = 0; np < 4; ++np) {
                uint32_t bh[4], bl[4];
                ldsm4(bh, sb + oBh + boB + swz(wn * 64 + np * 16 + brow, s * 16 + bkh));
                ldsm4(bl, sb + oBl + boB + swz(wn * 64 + np * 16 + brow, s * 16 + bkh));
#pragma unroll
                for (int mt = 0; mt < 4; ++mt) {
#pragma unroll
                    for (int j = 0; j < 2; ++j) {
                        mma16816(c[mt][np * 2 + j], a[mt], bh[2 * j], bh[2 * j + 1]);
                        mma16816(c[mt][np * 2 + j], a[mt], bl[2 * j], bl[2 * j + 1]);
                    }
                }
            }
        }
        buf ^= 1;
    }

    float* Yp = g_Yp[kz][br];
    const int lr = lane >> 2, lc = (lane & 3) * 2;
#pragma unroll
    for (int mt = 0; mt < 4; ++mt)
#pragma unroll
        for (int nt = 0; nt < 8; ++nt) {
            int m = m0 + wm * 64 + mt * 16 + lr;
            int n = wn * 64 + nt * 8 + lc;
            *(float2*)&Yp[m * 256 + n] = make_float2(c[mt][nt][0], c[mt][nt][1]);
            *(float2*)&Yp[(m + 8) * 256 + n] = make_float2(c[mt][nt][2], c[mt][nt][3]);
        }
}

// ========== small GEMM via mma.sync, batched over 4 branches ================
// AY: A := X + (Yp0 + Yp1)  (fused combine_Y, identical arithmetic order)
// XT: epilogue also emits X^T bf16 hi/lo (fused xt_split, identical values)
// CS: 1 = colsum of emitted bf16 H (EPI==2); 2 = col sum+sumsq of Hm (EPI==1)
#define SM_SMEM 81920
template <int ABN, int EPI, int AY, int XT, int CS>
__global__ __launch_bounds__(256, 1) void gemm_mma(
    const float* __restrict__ a0, const float* __restrict__ a1,
    const float* __restrict__ a2, const float* __restrict__ a3, int mat,
    const float* __restrict__ b0, const float* __restrict__ b1,
    const float* __restrict__ b2, const float* __restrict__ b3)
{
    extern __shared__ __align__(16) char smem[];
    const uint32_t sb = smem_u32(smem);
    const int tid = threadIdx.x, wid = tid >> 5, lane = tid & 31;
    const int n0 = blockIdx.x * 128, m0 = blockIdx.y * 64;
    const int br = blockIdx.z;
    const float* As4[4] = {a0, a1, a2, a3};
    const float* Bs4[4] = {b0, b1, b2, b3};
    const float* A = As4[br];
    const float* bias = Bs4[br];
    const float* Yp0 = g_Yp[0][br];
    const float* Yp1 = g_Yp[1][br];
    const int ws = wset_of(br);
    const __nv_bfloat16* Wth = g_Wth[ws][mat];
    const __nv_bfloat16* Wtl = g_Wtl[ws][mat];
    const int wm = wid >> 2, wn = wid & 3;   // warp tile 32m x 32n

    const uint32_t oAh = 0, oAl = 8192, oBh = 16384, oBl = 49152;
    const int arow = lane & 15, akh = (lane >> 4) * 8;
    const int brow = ((lane >> 4) << 3) + (lane & 7), bkh = ((lane >> 3) & 1) * 8;

    auto issueB = [&](int ch, int buf) {
        const int kb = ch * 64;
        const uint32_t bo = buf * 16384;
#pragma unroll
        for (int t = 0; t < 4; ++t) {
            int idx = tid + t * 256;
            int r = idx >> 3, g = (idx & 7) * 8;
            uint32_t so = swz(r, g);
            cp16(sb + oBh + bo + so, Wth + (n0 + r) * 256 + kb + g);
            cp16(sb + oBl + bo + so, Wtl + (n0 + r) * 256 + kb + g);
        }
    };
    auto loadA = [&](int ch) {
        const int kb = ch * 64;
#pragma unroll
        for (int t = 0; t < 2; ++t) {
            int idx = tid + t * 256;
            int r = idx >> 3, g = (idx & 7) * 8;
            const size_t off = (size_t)(m0 + r) * 256 + kb + g;
            float v[8];
            *(float4*)&v[0] = *(const float4*)(A + off);
            *(float4*)&v[4] = *(const float4*)(A + off + 4);
            if (AY) {
                float p0[8], p1[8];
                *(float4*)&p0[0] = *(const float4*)(Yp0 + off);
                *(float4*)&p0[4] = *(const float4*)(Yp0 + off + 4);
                *(float4*)&p1[0] = *(const float4*)(Yp1 + off);
                *(float4*)&p1[4] = *(const float4*)(Yp1 + off + 4);
#pragma unroll
                for (int j = 0; j < 8; ++j) v[j] = v[j] + (p0[j] + p1[j]);
            }
            if (ABN) {
                float4 s0 = *(const float4*)&g_bnscale[br][kb + g];
                float4 s1 = *(const float4*)&g_bnscale[br][kb + g + 4];
                float4 h0 = *(const float4*)&g_bnshift[br][kb + g];
                float4 h1 = *(const float4*)&g_bnshift[br][kb + g + 4];
                float sc[8] = {s0.x, s0.y, s0.z, s0.w, s1.x, s1.y, s1.z, s1.w};
                float sh[8] = {h0.x, h0.y, h0.z, h0.w, h1.x, h1.y, h1.z, h1.w};
#pragma unroll
                for (int j = 0; j < 8; ++j) v[j] = fmaxf(v[j] * sc[j] + sh[j], 0.0f);
            }
            float hi[8], lo[8];
#pragma unroll
            for (int j = 0; j < 8; ++j) {
                hi[j] = __bfloat162float(__float2bfloat16(v[j]));
                lo[j] = v[j] - hi[j];
            }
            *(uint4*)(smem + oAh + swz(r, g)) =
                make_uint4(bf2pack(hi[0], hi[1]), bf2pack(hi[2], hi[3]),
                           bf2pack(hi[4], hi[5]), bf2pack(hi[6], hi[7]));
            *(uint4*)(smem + oAl + swz(r, g)) =
                make_uint4(bf2pack(lo[0], lo[1]), bf2pack(lo[2], lo[3]),
                           bf2pack(lo[4], lo[5]), bf2pack(lo[6], lo[7]));
        }
    };

    float c[2][4][4] = {};
    issueB(0, 0);
    CP_COMMIT();
    int buf = 0;

    for (int ch = 0; ch < 4; ++ch) {
        CP_WAIT0();
        __syncthreads();
        if (ch < 3) { issueB(ch + 1, buf ^ 1); CP_COMMIT(); }
        loadA(ch);
        __syncthreads();
        const uint32_t boB = buf * 16384;
#pragma unroll
        for (int s = 0; s < 4; ++s) {
            uint32_t ah[2][4], al[2][4];
#pragma unroll
            for (int mt = 0; mt < 2; ++mt) {
                ldsm4(ah[mt], sb + oAh + swz(wm * 32 + mt * 16 + arow, s * 16 + akh));
                ldsm4(al[mt], sb + oAl + swz(wm * 32 + mt * 16 + arow, s * 16 + akh));
            }
#pragma unroll
            for (int np = 0; np < 2; ++np) {
                uint32_t bh[4], bl[4];
                ldsm4(bh, sb + oBh + boB + swz(wn * 32 + np * 16 + brow, s * 16 + bkh));
                ldsm4(bl, sb + oBl + boB + swz(wn * 32 + np * 16 + brow, s * 16 + bkh));
#pragma unroll
                for (int mt = 0; mt < 2; ++mt) {
#pragma unroll
                    for (int j = 0; j < 2; ++j) {
                        mma16816(c[mt][np * 2 + j], ah[mt], bh[2 * j], bh[2 * j + 1]);
                        mma16816(c[mt][np * 2 + j], ah[mt], bl[2 * j], bl[2 * j + 1]);
                        mma16816(c[mt][np * 2 + j], al[mt], bh[2 * j], bh[2 * j + 1]);
                    }
                }
            }
        }
        buf ^= 1;
    }

    // epilogue smem reuse: XT transpose buffers OR CS staging buffer [64][132]
    __nv_bfloat16* Th = reinterpret_cast<__nv_bfloat16*>(smem);        // [128][72]
    __nv_bfloat16* Tl = Th + 128 * 72;
    float* SV = reinterpret_cast<float*>(smem);                        // [64][132]
    if (XT || CS) __syncthreads();   // mainloop smem no longer needed

    const int lr = lane >> 2, lc = (lane & 3) * 2;
#pragma unroll
    for (int mt = 0; mt < 2; ++mt)
#pragma unroll
        for (int nt = 0; nt < 4; ++nt) {
            const int n = n0 + wn * 32 + nt * 8 + lc;
            float2 bv = *(const float2*)&bias[n];
#pragma unroll
            for (int h = 0; h < 2; ++h) {
                const int m = m0 + wm * 32 + mt * 16 + lr + h * 8;
                const int lm = m - m0;                 // 0..63
                const int ln = wn * 32 + nt * 8 + lc;  // 0..127
                float v0 = c[mt][nt][h * 2 + 0] + bv.x;
                float v1 = c[mt][nt][h * 2 + 1] + bv.y;
                if (EPI == 0 || EPI == 2) { v0 = eluf(v0); v1 = eluf(v1); }
                if (EPI == 0) {
                    *(float2*)&g_H1[br][m * 256 + n] = make_float2(v0, v1);
                } else if (EPI == 1) {
                    *(float2*)&g_Hm[br][m * 256 + n] = make_float2(v0, v1);
                    if (CS == 2) {
                        SV[lm * 132 + ln] = v0;
                        SV[lm * 132 + ln + 1] = v1;
                    }
                } else if (EPI == 2) {
                    float h0 = __bfloat162float(__float2bfloat16(v0));
                    float h1 = __bfloat162float(__float2bfloat16(v1));
                    float l0 = __bfloat162float(__float2bfloat16(v0 - h0));
                    float l1 = __bfloat162float(__float2bfloat16(v1 - h1));
                    *(uint32_t*)&g_Hh[br][m * 256 + n] = bf2pack(h0, h1);
                    *(uint32_t*)&g_Hl[br][m * 256 + n] = bf2pack(v0 - h0, v1 - h1);
                    if (CS == 1) {
                        SV[lm * 132 + ln] = h0 + l0;
                        SV[lm * 132 + ln + 1] = h1 + l1;
                    }
                } else if (EPI == 5) {
                    float2 ac = *(const float2*)&g_ACC[br][m * 256 + n];
                    *(float2*)&g_G[br][m * 256 + n] =
                        make_float2((ac.x + v0) * (1.0f / 3.0f),
                                    (ac.y + v1) * (1.0f / 3.0f));
                } else {
                    *(float2*)&g_X[br][m * 256 + n] = make_float2(v0, v1);
                    if (EPI == 3)
                        *(float2*)&g_ACC[br][m * 256 + n] = make_float2(v0, v1);
                    if (EPI == 4) {
                        float2 ac = *(const float2*)&g_ACC[br][m * 256 + n];
                        *(float2*)&g_ACC[br][m * 256 + n] =
                            make_float2(ac.x + v0, ac.y + v1);
                    }
                    if (XT) {
                        __nv_bfloat16 h0 = __float2bfloat16(v0);
                        __nv_bfloat16 h1 = __float2bfloat16(v1);
                        Th[ln * 72 + lm] = h0;
                        Th[(ln + 1) * 72 + lm] = h1;
                        Tl[ln * 72 + lm] = __float2bfloat16(v0 - __bfloat162float(h0));
                        Tl[(ln + 1) * 72 + lm] = __float2bfloat16(v1 - __bfloat162float(h1));
                    }
                }
            }
        }

    if (XT) {
        __syncthreads();
        const int row = tid & 127;
        const bool lo = tid >= 128;
        const __nv_bfloat16* src = (lo ? Tl : Th) + row * 72;
        __nv_bfloat16* dst = (lo ? g_Xtl[br] : g_Xth[br]) + (n0 + row) * 4096 + m0;
#pragma unroll
        for (int q = 0; q < 8; ++q)
            reinterpret_cast<uint4*>(dst)[q] =
                reinterpret_cast<const uint4*>(src)[q];
    }
    if (CS) {
        __syncthreads();
        if (tid < 128) {
            float s = 0.0f, q = 0.0f;
            for (int mm = 0; mm < 64; ++mm) {
                float v = SV[mm * 132 + tid];
                s += v;
                if (CS == 2) q += v * v;
            }
            if (CS == 1) {
                g_sumpart[br][blockIdx.y][n0 + tid] = s;
            } else {
                g_colpart[br][blockIdx.y * 512 + n0 + tid] = s;
                g_colpart[br][blockIdx.y * 512 + 256 + n0 + tid] = q;
            }
        }
    }
}

// =============== weight transpose + bf16 split (3 sets x 8 mats) ============
__global__ void wt_split(const float* __restrict__ aw0, const float* __restrict__ aw1,
                         const float* __restrict__ aw2, const float* __restrict__ mw0,
                         const float* __restrict__ mw1, const float* __restrict__ mw2)
{
    const int z = blockIdx.z, ws = z >> 3, mat = z & 7;
    const float* aws[3] = {aw0, aw1, aw2};
    const float* mws[3] = {mw0, mw1, mw2};
    const float* src = (mat < 2) ? aws[ws] + mat * 65536 : mws[ws] + (mat - 2) * 65536;
    __shared__ float t[32][33];
    const int r0 = blockIdx.x * 32, c0 = blockIdx.y * 32;
    const int x = threadIdx.x, y = threadIdx.y;
    for (int i = 0; i < 32; i += 8)
        t[y + i][x] = src[(r0 + y + i) * 256 + c0 + x];
    __syncthreads();
    for (int i = 0; i < 32; i += 8) {
        float v = t[x][y + i];
        __nv_bfloat16 h = __float2bfloat16(v);
        float hf = __bfloat162float(h);
        g_Wth[ws][mat][(c0 + y + i) * 256 + r0 + x] = h;
        g_Wtl[ws][mat][(c0 + y + i) * 256 + r0 + x] = __float2bfloat16(v - hf);
    }
}

// =============== X transpose + bf16 split, batched (layer 0 only) ===========
__global__ void xt_split(const float* __restrict__ x0, const float* __restrict__ x1,
                         const float* __restrict__ x2, const float* __restrict__ x3)
{
    const int br = blockIdx.z;
    const float* Xs[4] = {x0, x1, x2, x3};
    const float* X = Xs[br];
    __shared__ float t[32][33];
    const int r0 = blockIdx.x * 32, c0 = blockIdx.y * 32;
    const int x = threadIdx.x, y = threadIdx.y;
    for (int i = 0; i < 32; i += 8)
        t[y + i][x] = X[(r0 + y + i) * 256 + c0 + x];
    __syncthreads();
    for (int i = 0; i < 32; i += 8) {
        float v = t[x][y + i];
        __nv_bfloat16 h = __float2bfloat16(v);
        float hf = __bfloat162float(h);
        g_Xth[br][(c0 + y + i) * 4096 + r0 + x] = h;
        g_Xtl[br][(c0 + y + i) * 4096 + r0 + x] = __float2bfloat16(v - hf);
    }
}

// ---------------- BN finalize (partials from gemm<0,1> epilogue) ------------
__global__ void finalize_stats(const float* __restrict__ g0, const float* __restrict__ g1,
                               const float* __restrict__ g2, const float* __restrict__ g3)
{
    const int br = blockIdx.x, t = threadIdx.x;
    const float* Gs[4] = {g0, g1, g2, g3};
    const float* gamma = Gs[br];
    const float* beta = gamma + 256;
    float s = 0.0f, q = 0.0f;
    for (int b = 0; b < 64; ++b) {
        s += g_colpart[br][b * 512 + t];
        q += g_colpart[br][b * 512 + 256 + t];
    }
    float mu = s * (1.0f / (float)NN);
    float var = q * (1.0f / (float)NN) - mu * mu;
    float rstd = rsqrtf(var + 1e-5f);
    float sc = gamma[t] * rstd;
    g_bnscale[br][t] = sc;
    g_bnshift[br][t] = beta[t] - mu * sc;
}

// ---------------- MSE --------------------------------------------------------
__global__ void mse_partial()
{
    int t = threadIdx.x, b = blockIdx.x;
    float s0 = 0.0f, s1 = 0.0f, s2 = 0.0f;
    for (int i = b * 256 + t; i < ND; i += 256 * 256) {
        float ga = g_G[3][i];
        float d0 = g_G[0][i] - ga;
        float d1 = g_G[1][i] - ga;
        float d2 = g_G[2][i] - ga;
        s0 += d0 * d0;
        s1 += d1 * d1;
        s2 += d2 * d2;
    }
    __shared__ float r[3][256];
    r[0][t] = s0; r[1][t] = s1; r[2][t] = s2;
    __syncthreads();
    for (int o = 128; o > 0; o >>= 1) {
        if (t < o) {
            r[0][t] += r[0][t + o];
            r[1][t] += r[1][t + o];
            r[2][t] += r[2][t + o];
        }
        __syncthreads();
    }
    if (t == 0) {
        g_msepart[b * 3 + 0] = r[0][0];
        g_msepart[b * 3 + 1] = r[1][0];
        g_msepart[b * 3 + 2] = r[2][0];
    }
}

__global__ void mse_final(float* __restrict__ out)
{
    int t = threadIdx.x;
    __shared__ float r[256];
    for (int v = 0; v < 3; ++v) {
        r[t] = g_msepart[t * 3 + v];
        __syncthreads();
        for (int o = 128; o > 0; o >>= 1) {
            if (t < o) r[t] += r[t + o];
            __syncthreads();
        }
        if (t == 0) out[v] = r[0] * (1.0f / (float)ND);
        __syncthreads();
    }
}

// ---------------- host driver ------------------------------------------------
extern "C" void kernel_launch(void* const* d_in, const int* in_sizes, int n_in,
                              void* d_out, int out_size)
{
    const float* QV = (const float*)d_in[0];
    const float* Q  = (const float*)d_in[1];
    const float* V  = (const float*)d_in[2];
    const float* A  = (const float*)d_in[3];
    const float* adjW_qv  = (const float*)d_in[4];
    const float* adjb_qv  = (const float*)d_in[5];
    const float* mlpW_qv  = (const float*)d_in[6];
    const float* mlpb_qv  = (const float*)d_in[7];
    const float* mlpbn_qv = (const float*)d_in[8];
    const float* adjW_t   = (const float*)d_in[9];
    const float* adjb_t   = (const float*)d_in[10];
    const float* mlpW_t   = (const float*)d_in[11];
    const float* mlpb_t   = (const float*)d_in[12];
    const float* mlpbn_t  = (const float*)d_in[13];
    const float* adjW_v   = (const float*)d_in[14];
    const float* adjb_v   = (const float*)d_in[15];
    const float* mlpW_v   = (const float*)d_in[16];
    const float* mlpb_v   = (const float*)d_in[17];
    const float* mlpbn_v  = (const float*)d_in[18];

    cudaFuncSetAttribute(adj_mma, cudaFuncAttributeMaxDynamicSharedMemorySize, ADJ_SMEM);
    cudaFuncSetAttribute(thresh_mma, cudaFuncAttributeMaxDynamicSharedMemorySize, THR_SMEM);
    cudaFuncSetAttribute(gemm_mma<0, 0, 0, 0, 0>, cudaFuncAttributeMaxDynamicSharedMemorySize, SM_SMEM);
    cudaFuncSetAttribute(gemm_mma<0, 1, 1, 0, 2>, cudaFuncAttributeMaxDynamicSharedMemorySize, SM_SMEM);
    cudaFuncSetAttribute(gemm_mma<0, 2, 0, 0, 1>, cudaFuncAttributeMaxDynamicSharedMemorySize, SM_SMEM);
    cudaFuncSetAttribute(gemm_mma<1, 3, 0, 1, 0>, cudaFuncAttributeMaxDynamicSharedMemorySize, SM_SMEM);
    cudaFuncSetAttribute(gemm_mma<1, 4, 0, 1, 0>, cudaFuncAttributeMaxDynamicSharedMemorySize, SM_SMEM);
    cudaFuncSetAttribute(gemm_mma<1, 5, 0, 0, 0>, cudaFuncAttributeMaxDynamicSharedMemorySize, SM_SMEM);

    float *pX, *pH1, *pHm;
    cudaGetSymbolAddress((void**)&pX, g_X);
    cudaGetSymbolAddress((void**)&pH1, g_H1);
    cudaGetSymbolAddress((void**)&pHm, g_Hm);

    const float* ab[4] = {adjb_qv, adjb_t, adjb_v, adjb_t};
    const float* mb[4] = {mlpb_qv, mlpb_t, mlpb_v, mlpb_t};
    const float* bn[4] = {mlpbn_qv, mlpbn_t, mlpbn_v, mlpbn_t};

    wt_split<<<dim3(8, 8, 24), dim3(32, 8)>>>(adjW_qv, adjW_t, adjW_v,
                                              mlpW_qv, mlpW_t, mlpW_v);

    const dim3 g_sm(2, 64, 4);
    for (int l = 0; l < LL; ++l) {
        const float* X0 = (l == 0) ? QV : pX;
        const float* X1 = (l == 0) ? Q : pX + (size_t)ND;
        const float* X2 = (l == 0) ? V : pX + 2 * (size_t)ND;
        const float* X3 = (l == 0) ? A : pX + 3 * (size_t)ND;

        gemm_mma<0, 0, 0, 0, 0><<<g_sm, 256, SM_SMEM>>>(X0, X1, X2, X3, 0,
                                                        ab[0], ab[1], ab[2], ab[3]);
        // emits Hh/Hl AND per-block column sums (fused colsum_part)
        gemm_mma<0, 2, 0, 0, 1><<<g_sm, 256, SM_SMEM>>>(
            pH1, pH1 + (size_t)ND, pH1 + 2 * (size_t)ND, pH1 + 3 * (size_t)ND, 1,
            ab[0] + 256, ab[1] + 256, ab[2] + 256, ab[3] + 256);
        colsum_mean<<<4, 256>>>();
        adj_mma<<<dim3(NTB, 4), 256, ADJ_SMEM>>>();
        if (l == 0)   // layers 1..2 get X^T from the previous gemm's epilogue
            xt_split<<<dim3(128, 8, 4), dim3(32, 8)>>>(X0, X1, X2, X3);
        thresh_mma<<<dim3(32, KZ, 4), 256, THR_SMEM>>>();

        // MLP GEMM 1: fused Y = X + (Yp0+Yp1) on A-path + fused colstats
        gemm_mma<0, 1, 1, 0, 2><<<g_sm, 256, SM_SMEM>>>(
            X0, X1, X2, X3, 2 + 2 * l,
            mb[0] + l * 512, mb[1] + l * 512, mb[2] + l * 512, mb[3] + l * 512);
        finalize_stats<<<4, 256>>>(bn[0] + l * 512, bn[1] + l * 512,
                                   bn[2] + l * 512, bn[3] + l * 512);
        const float* c0 = mb[0] + l * 512 + 256;
        const float* c1 = mb[1] + l * 512 + 256;
        const float* c2 = mb[2] + l * 512 + 256;
        const float* c3 = mb[3] + l * 512 + 256;
        if (l == 0)
            gemm_mma<1, 3, 0, 1, 0><<<g_sm, 256, SM_SMEM>>>(
                pHm, pHm + (size_t)ND, pHm + 2 * (size_t)ND, pHm + 3 * (size_t)ND,
                3 + 2 * l, c0, c1, c2, c3);
        else if (l == 1)
            gemm_mma<1, 4, 0, 1, 0><<<g_sm, 256, SM_SMEM>>>(
                pHm, pHm + (size_t)ND, pHm + 2 * (size_t)ND, pHm + 3 * (size_t)ND,
                3 + 2 * l, c0, c1, c2, c3);
        else
            gemm_mma<1, 5, 0, 0, 0><<<g_sm, 256, SM_SMEM>>>(
                pHm, pHm + (size_t)ND, pHm + 2 * (size_t)ND, pHm + 3 * (size_t)ND,
                3 + 2 * l, c0, c1, c2, c3);
    }

    mse_partial<<<256, 256>>>();
    mse_final<<<1, 256>>>((float*)d_out);
}